// round 14
// baseline (speedup 1.0000x reference)
#include <cuda_runtime.h>
#include <cuda_fp16.h>
#include <cstdint>

// Problem constants (fixed by the reference).
#define BB 4
#define CC 64
#define TT 8
#define HH 128
#define WW 128
#define DG 8
#define CG 8            // channels per deformable group = CC/DG
#define HW (HH*WW)      // 16384
#define THW (TT*HH*WW)  // 131072

// Bit-cast helpers.
__device__ __forceinline__ unsigned h2_to_u(__half2 h) {
    union { __half2 h; unsigned u; } c; c.h = h; return c.u;
}
__device__ __forceinline__ __half2 u_to_h2(unsigned u) {
    union { unsigned u; __half2 h; } c; c.u = u; return c.h;
}

// Channel-last fp16 scratch: xT[b][g][t][h][w][c8] (16 B per pixel-group).
__device__ __half g_xT[(size_t)BB * DG * TT * HH * WW * CG];
// Sampled values (fp32) for the general-weight path.
__device__ float g_samp[(size_t)BB * DG * TT * HW * CG];

// Flag: 0 if weight==Identity and bias==0 (fast path), 1 otherwise.
__device__ int g_general;

// Transpose one batch b: [C,T,H,W] fp32 -> [G,T,H,W,C8] fp16. No smem.
// Chunk b==0, block 0 additionally computes g_general from weight/bias.
__global__ __launch_bounds__(256, 8)
void transpose_kernel(const float* __restrict__ x,
                      const float* __restrict__ wgt,
                      const float* __restrict__ bias,
                      const int b) {
    if (b == 0 && blockIdx.x == 0) {
        __shared__ int sbad;
        if (threadIdx.x == 0) sbad = 0;
        __syncthreads();
        int bad = 0;
        for (int i = threadIdx.x; i < CC * CC; i += 256) {
            float e = ((i >> 6) == (i & 63)) ? 1.0f : 0.0f;
            if (wgt[i] != e) bad = 1;
        }
        if (threadIdx.x < CC && bias[threadIdx.x] != 0.0f) bad = 1;
        if (bad) atomicOr(&sbad, 1);
        __syncthreads();
        if (threadIdx.x == 0) g_general = sbad;
        __syncthreads();
    }

    // Chunk-local linear index over [DG][T][H][W].
    const int p  = blockIdx.x * 256 + threadIdx.x;
    const int hw = p & (HW - 1);
    const int t  = (p >> 14) & 7;
    const int g  = (p >> 17) & 7;

    // Streaming reads: x is read exactly once; don't pollute L2 with it.
    const float* src = x + ((size_t)(b * CC + g * CG) * TT + t) * HW + hw;
    float v0 = __ldcs(src);
    float v1 = __ldcs(src + THW);
    float v2 = __ldcs(src + 2 * THW);
    float v3 = __ldcs(src + 3 * THW);
    float v4 = __ldcs(src + 4 * THW);
    float v5 = __ldcs(src + 5 * THW);
    float v6 = __ldcs(src + 6 * THW);
    float v7 = __ldcs(src + 7 * THW);

    uint4 o;
    o.x = h2_to_u(__floats2half2_rn(v0, v1));
    o.y = h2_to_u(__floats2half2_rn(v2, v3));
    o.z = h2_to_u(__floats2half2_rn(v4, v5));
    o.w = h2_to_u(__floats2half2_rn(v6, v7));
    ((uint4*)g_xT)[(size_t)b * (DG * THW) + p] = o;
}

// Gather for one batch b. Block = (g, 8h x 32w tile), looping t = 0..7.
// 512 threads = 256 pixels x 2 w-corner threads; 4 blocks/SM target.
__global__ __launch_bounds__(512, 4)
void deform_kernel(const float* __restrict__ off,
                   float* __restrict__ out,
                   const int b) {
    const int n  = blockIdx.x;
    const int wt = n & 3;            // w tile (4)
    const int ht = (n >> 2) & 15;    // h tile (16)
    const int g  = n >> 6;           // 0..7

    const int wq = threadIdx.x & 1;          // w-corner select
    const int wl = (threadIdx.x >> 1) & 31;
    const int hl = threadIdx.x >> 6;         // 0..7
    const int w  = (wt << 5) + wl;
    const int h  = (ht << 3) + hl;

    const char* bg  = (const char*)(g_xT + (size_t)(b * DG + g) * THW * CG);
    const int   so0 = ((b * (3 * DG) + g * 3) * TT) * HW + h * WW + w;

    // Prologue: load offsets for t=0 (streaming — read once).
    float ot = __ldcs(off + so0);
    float oh = __ldcs(off + so0 + THW);
    float ow = __ldcs(off + so0 + 2 * THW);

    for (int t = 0; t < TT; ++t) {
        const float gt = (float)t + ot;
        const float gh = (float)h + oh;
        const float gw = (float)w + ow;

        // Pipelined load of next iteration's offsets.
        if (t + 1 < TT) {
            const int so = so0 + (t + 1) * HW;
            ot = __ldcs(off + so);
            oh = __ldcs(off + so + THW);
            ow = __ldcs(off + so + 2 * THW);
        }

        const float ftf = floorf(gt), fhf = floorf(gh), fwf = floorf(gw);
        const int   t0 = (int)ftf,    h0 = (int)fhf,    w0 = (int)fwf;
        const float dt = gt - ftf,    dh = gh - fhf,    dw = gw - fwf;

        float wta0 = (1.0f - dt) * (((unsigned)t0       < (unsigned)TT) ? 1.0f : 0.0f);
        float wta1 = dt          * (((unsigned)(t0 + 1) < (unsigned)TT) ? 1.0f : 0.0f);
        float whb0 = (1.0f - dh) * (((unsigned)h0       < (unsigned)HH) ? 1.0f : 0.0f);
        float whb1 = dh          * (((unsigned)(h0 + 1) < (unsigned)HH) ? 1.0f : 0.0f);
        const int tc0 = min(TT - 1, max(0, t0));
        const int tc1 = min(TT - 1, max(0, t0 + 1));
        const int hc0 = min(HH - 1, max(0, h0));
        const int hc1 = min(HH - 1, max(0, h0 + 1));

        // This thread's w-corner.
        const int   wcm = w0 + wq;
        const float wwq = (wq ? dw : (1.0f - dw))
                        * (((unsigned)wcm < (unsigned)WW) ? 1.0f : 0.0f);
        const unsigned wb = (unsigned)min(WW - 1, max(0, wcm)) * 16u;

        // 32-bit row byte-offsets within this (b,g) slice (< 2 MB).
        const unsigned RB = (unsigned)(WW * CG * 2);   // bytes per row
        const unsigned r00 = (unsigned)(tc0 * HH + hc0) * RB + wb;
        const unsigned r01 = (unsigned)(tc0 * HH + hc1) * RB + wb;
        const unsigned r10 = (unsigned)(tc1 * HH + hc0) * RB + wb;
        const unsigned r11 = (unsigned)(tc1 * HH + hc1) * RB + wb;

        float acc0 = 0.f, acc1 = 0.f, acc2 = 0.f, acc3 = 0.f;
        float acc4 = 0.f, acc5 = 0.f, acc6 = 0.f, acc7 = 0.f;

        // t-corner 0: two gathers, then FMA.
        {
            uint4 ua = __ldg((const uint4*)(bg + r00));
            uint4 ub = __ldg((const uint4*)(bg + r01));
            const float wc_a = wta0 * whb0 * wwq;
            const float wc_b = wta0 * whb1 * wwq;
            float2 f;
            f = __half22float2(u_to_h2(ua.x)); acc0 = fmaf(wc_a, f.x, acc0); acc1 = fmaf(wc_a, f.y, acc1);
            f = __half22float2(u_to_h2(ua.y)); acc2 = fmaf(wc_a, f.x, acc2); acc3 = fmaf(wc_a, f.y, acc3);
            f = __half22float2(u_to_h2(ua.z)); acc4 = fmaf(wc_a, f.x, acc4); acc5 = fmaf(wc_a, f.y, acc5);
            f = __half22float2(u_to_h2(ua.w)); acc6 = fmaf(wc_a, f.x, acc6); acc7 = fmaf(wc_a, f.y, acc7);
            f = __half22float2(u_to_h2(ub.x)); acc0 = fmaf(wc_b, f.x, acc0); acc1 = fmaf(wc_b, f.y, acc1);
            f = __half22float2(u_to_h2(ub.y)); acc2 = fmaf(wc_b, f.x, acc2); acc3 = fmaf(wc_b, f.y, acc3);
            f = __half22float2(u_to_h2(ub.z)); acc4 = fmaf(wc_b, f.x, acc4); acc5 = fmaf(wc_b, f.y, acc5);
            f = __half22float2(u_to_h2(ub.w)); acc6 = fmaf(wc_b, f.x, acc6); acc7 = fmaf(wc_b, f.y, acc7);
        }
        // t-corner 1: two gathers, then FMA.
        {
            uint4 ua = __ldg((const uint4*)(bg + r10));
            uint4 ub = __ldg((const uint4*)(bg + r11));
            const float wc_a = wta1 * whb0 * wwq;
            const float wc_b = wta1 * whb1 * wwq;
            float2 f;
            f = __half22float2(u_to_h2(ua.x)); acc0 = fmaf(wc_a, f.x, acc0); acc1 = fmaf(wc_a, f.y, acc1);
            f = __half22float2(u_to_h2(ua.y)); acc2 = fmaf(wc_a, f.x, acc2); acc3 = fmaf(wc_a, f.y, acc3);
            f = __half22float2(u_to_h2(ua.z)); acc4 = fmaf(wc_a, f.x, acc4); acc5 = fmaf(wc_a, f.y, acc5);
            f = __half22float2(u_to_h2(ua.w)); acc6 = fmaf(wc_a, f.x, acc6); acc7 = fmaf(wc_a, f.y, acc7);
            f = __half22float2(u_to_h2(ub.x)); acc0 = fmaf(wc_b, f.x, acc0); acc1 = fmaf(wc_b, f.y, acc1);
            f = __half22float2(u_to_h2(ub.y)); acc2 = fmaf(wc_b, f.x, acc2); acc3 = fmaf(wc_b, f.y, acc3);
            f = __half22float2(u_to_h2(ub.z)); acc4 = fmaf(wc_b, f.x, acc4); acc5 = fmaf(wc_b, f.y, acc5);
            f = __half22float2(u_to_h2(ub.w)); acc6 = fmaf(wc_b, f.x, acc6); acc7 = fmaf(wc_b, f.y, acc7);
        }

        // Combine the two w-corners (lane pairs differ only in bit0).
        acc0 += __shfl_xor_sync(0xFFFFFFFFu, acc0, 1);
        acc1 += __shfl_xor_sync(0xFFFFFFFFu, acc1, 1);
        acc2 += __shfl_xor_sync(0xFFFFFFFFu, acc2, 1);
        acc3 += __shfl_xor_sync(0xFFFFFFFFu, acc3, 1);
        acc4 += __shfl_xor_sync(0xFFFFFFFFu, acc4, 1);
        acc5 += __shfl_xor_sync(0xFFFFFFFFu, acc5, 1);
        acc6 += __shfl_xor_sync(0xFFFFFFFFu, acc6, 1);
        acc7 += __shfl_xor_sync(0xFFFFFFFFu, acc7, 1);

        if (wq == 0) {
            if (!g_general) {
                // Streaming stores: out is write-once, keep it out of L2.
                float* ob = out + ((size_t)(b * CC + g * CG) * TT + t) * HW
                                + (size_t)h * WW + w;
                __stcs(ob,           acc0);
                __stcs(ob + THW,     acc1);
                __stcs(ob + 2*THW,   acc2);
                __stcs(ob + 3*THW,   acc3);
                __stcs(ob + 4*THW,   acc4);
                __stcs(ob + 5*THW,   acc5);
                __stcs(ob + 6*THW,   acc6);
                __stcs(ob + 7*THW,   acc7);
            } else {
                float* dst = g_samp + ((size_t)(b * DG + g) * THW
                             + (size_t)t * HW + (size_t)h * WW + w) * CG;
                ((float4*)dst)[0] = make_float4(acc0, acc1, acc2, acc3);
                ((float4*)dst)[1] = make_float4(acc4, acc5, acc6, acc7);
            }
        }
    }
}

// General 1x1x1 conv path (early-exits when weight is identity).
__global__ __launch_bounds__(256, 4)
void conv_kernel(const float* __restrict__ wgt,
                 const float* __restrict__ bias,
                 float* __restrict__ out) {
    if (!g_general) return;
    const int base = (blockIdx.x * 256 + threadIdx.x) * 8;
#pragma unroll 1
    for (int k = 0; k < 8; k++) {
        const int p = base + k;                 // pixel in [0, B*THW)
        const int b = p / THW;
        const int r = p - b * THW;

        float sv[CC];
#pragma unroll
        for (int g = 0; g < DG; g++) {
            const float* src = g_samp + ((size_t)(b * DG + g) * THW + r) * CG;
#pragma unroll
            for (int c = 0; c < CG; c++) sv[g * CG + c] = src[c];
        }
#pragma unroll 4
        for (int o = 0; o < CC; o++) {
            float a = bias[o];
#pragma unroll 16
            for (int c = 0; c < CC; c++)
                a = fmaf(wgt[o * CC + c], sv[c], a);
            out[(size_t)(b * CC + o) * THW + r] = a;
        }
    }
}

extern "C" void kernel_launch(void* const* d_in, const int* in_sizes, int n_in,
                              void* d_out, int out_size) {
    const float* x    = (const float*)d_in[0];
    const float* off  = (const float*)d_in[1];
    const float* wgt  = (const float*)d_in[2];
    const float* bias = (const float*)d_in[3];
    float* out = (float*)d_out;

    // Two-stream software pipeline: transpose chunk b on s1 overlaps deform
    // chunk b-1 on the main (capturing) stream. Event record/wait become
    // graph dependencies under capture. Streams/events are intentionally not
    // destroyed: destroying a capture-participating stream invalidates the
    // capture, and these are host-side handles (no tracked device memory).
    cudaStream_t s1;
    cudaStreamCreateWithFlags(&s1, cudaStreamNonBlocking);
    cudaEvent_t eFork;
    cudaEventCreateWithFlags(&eFork, cudaEventDisableTiming);
    cudaEventRecord(eFork, 0);
    cudaStreamWaitEvent(s1, eFork, 0);

    const int ntrans_b  = (DG * THW) / 256;   // 4096 blocks per batch chunk
    const int ndeform_b = DG * 16 * 4;        // 512 blocks per batch chunk

    for (int b = 0; b < BB; b++) {
        transpose_kernel<<<ntrans_b, 256, 0, s1>>>(x, wgt, bias, b);
        cudaEvent_t eT;
        cudaEventCreateWithFlags(&eT, cudaEventDisableTiming);
        cudaEventRecord(eT, s1);
        cudaStreamWaitEvent(0, eT, 0);
        deform_kernel<<<ndeform_b, 512>>>(off, out, b);
    }

    conv_kernel<<<(BB * THW) / (256 * 8), 256>>>(wgt, bias, out);
}

// round 15
// speedup vs baseline: 1.1176x; 1.1176x over previous
#include <cuda_runtime.h>
#include <cuda_fp16.h>
#include <cstdint>

// Problem constants (fixed by the reference).
#define BB 4
#define CC 64
#define TT 8
#define HH 128
#define WW 128
#define DG 8
#define CG 8            // channels per deformable group = CC/DG
#define HW (HH*WW)      // 16384
#define THW (TT*HH*WW)  // 131072

// Bit-cast helpers.
__device__ __forceinline__ unsigned h2_to_u(__half2 h) {
    union { __half2 h; unsigned u; } c; c.h = h; return c.u;
}
__device__ __forceinline__ __half2 u_to_h2(unsigned u) {
    union { unsigned u; __half2 h; } c; c.u = u; return c.h;
}

// Channel-last fp16 scratch: xT[b][g][t][h][w][c8] (16 B per pixel-group).
__device__ __half g_xT[(size_t)BB * DG * TT * HH * WW * CG];
// Sampled values (fp32) for the general-weight path.
__device__ float g_samp[(size_t)BB * DG * TT * HW * CG];

// Flag: 0 if weight==Identity and bias==0 (fast path), 1 otherwise.
__device__ int g_general;

// Transpose TWO batches [bbase, bbase+2): [C,T,H,W] fp32 -> [G,T,H,W,C8] fp16.
// Chunk bbase==0, block 0 additionally computes g_general from weight/bias.
__global__ __launch_bounds__(256, 8)
void transpose_kernel(const float* __restrict__ x,
                      const float* __restrict__ wgt,
                      const float* __restrict__ bias,
                      const int bbase) {
    if (bbase == 0 && blockIdx.x == 0) {
        __shared__ int sbad;
        if (threadIdx.x == 0) sbad = 0;
        __syncthreads();
        int bad = 0;
        for (int i = threadIdx.x; i < CC * CC; i += 256) {
            float e = ((i >> 6) == (i & 63)) ? 1.0f : 0.0f;
            if (wgt[i] != e) bad = 1;
        }
        if (threadIdx.x < CC && bias[threadIdx.x] != 0.0f) bad = 1;
        if (bad) atomicOr(&sbad, 1);
        __syncthreads();
        if (threadIdx.x == 0) g_general = sbad;
        __syncthreads();
    }

    // Chunk-local linear index over [2][DG][T][H][W].
    const int p  = blockIdx.x * 256 + threadIdx.x;
    const int hw = p & (HW - 1);
    const int t  = (p >> 14) & 7;
    const int g  = (p >> 17) & 7;
    const int b  = bbase + (p >> 20);

    // Streaming reads: x is read exactly once; don't pollute L2 with it.
    const float* src = x + ((size_t)(b * CC + g * CG) * TT + t) * HW + hw;
    float v0 = __ldcs(src);
    float v1 = __ldcs(src + THW);
    float v2 = __ldcs(src + 2 * THW);
    float v3 = __ldcs(src + 3 * THW);
    float v4 = __ldcs(src + 4 * THW);
    float v5 = __ldcs(src + 5 * THW);
    float v6 = __ldcs(src + 6 * THW);
    float v7 = __ldcs(src + 7 * THW);

    uint4 o;
    o.x = h2_to_u(__floats2half2_rn(v0, v1));
    o.y = h2_to_u(__floats2half2_rn(v2, v3));
    o.z = h2_to_u(__floats2half2_rn(v4, v5));
    o.w = h2_to_u(__floats2half2_rn(v6, v7));
    ((uint4*)g_xT)[(size_t)bbase * (DG * THW) + p] = o;
}

// Gather for TWO batches [bbase, bbase+2). Block = (b, g, 8h x 32w tile),
// looping t = 0..7. 512 threads = 256 pixels x 2 w-corner threads.
// 1024 blocks/chunk ~ 1.7 waves: keeps cross-wave load balancing.
__global__ __launch_bounds__(512, 4)
void deform_kernel(const float* __restrict__ off,
                   float* __restrict__ out,
                   const int bbase) {
    const int n  = blockIdx.x;
    const int wt = n & 3;            // w tile (4)
    const int ht = (n >> 2) & 15;    // h tile (16)
    const int g  = (n >> 6) & 7;
    const int b  = bbase + (n >> 9);

    const int wq = threadIdx.x & 1;          // w-corner select
    const int wl = (threadIdx.x >> 1) & 31;
    const int hl = threadIdx.x >> 6;         // 0..7
    const int w  = (wt << 5) + wl;
    const int h  = (ht << 3) + hl;

    const char* bg  = (const char*)(g_xT + (size_t)(b * DG + g) * THW * CG);
    const int   so0 = ((b * (3 * DG) + g * 3) * TT) * HW + h * WW + w;

    // Prologue: load offsets for t=0 (streaming — read once).
    float ot = __ldcs(off + so0);
    float oh = __ldcs(off + so0 + THW);
    float ow = __ldcs(off + so0 + 2 * THW);

    for (int t = 0; t < TT; ++t) {
        const float gt = (float)t + ot;
        const float gh = (float)h + oh;
        const float gw = (float)w + ow;

        // Pipelined load of next iteration's offsets.
        if (t + 1 < TT) {
            const int so = so0 + (t + 1) * HW;
            ot = __ldcs(off + so);
            oh = __ldcs(off + so + THW);
            ow = __ldcs(off + so + 2 * THW);
        }

        const float ftf = floorf(gt), fhf = floorf(gh), fwf = floorf(gw);
        const int   t0 = (int)ftf,    h0 = (int)fhf,    w0 = (int)fwf;
        const float dt = gt - ftf,    dh = gh - fhf,    dw = gw - fwf;

        float wta0 = (1.0f - dt) * (((unsigned)t0       < (unsigned)TT) ? 1.0f : 0.0f);
        float wta1 = dt          * (((unsigned)(t0 + 1) < (unsigned)TT) ? 1.0f : 0.0f);
        float whb0 = (1.0f - dh) * (((unsigned)h0       < (unsigned)HH) ? 1.0f : 0.0f);
        float whb1 = dh          * (((unsigned)(h0 + 1) < (unsigned)HH) ? 1.0f : 0.0f);
        const int tc0 = min(TT - 1, max(0, t0));
        const int tc1 = min(TT - 1, max(0, t0 + 1));
        const int hc0 = min(HH - 1, max(0, h0));
        const int hc1 = min(HH - 1, max(0, h0 + 1));

        // This thread's w-corner.
        const int   wcm = w0 + wq;
        const float wwq = (wq ? dw : (1.0f - dw))
                        * (((unsigned)wcm < (unsigned)WW) ? 1.0f : 0.0f);
        const unsigned wb = (unsigned)min(WW - 1, max(0, wcm)) * 16u;

        // 32-bit row byte-offsets within this (b,g) slice (< 2 MB).
        const unsigned RB = (unsigned)(WW * CG * 2);   // bytes per row
        const unsigned r00 = (unsigned)(tc0 * HH + hc0) * RB + wb;
        const unsigned r01 = (unsigned)(tc0 * HH + hc1) * RB + wb;
        const unsigned r10 = (unsigned)(tc1 * HH + hc0) * RB + wb;
        const unsigned r11 = (unsigned)(tc1 * HH + hc1) * RB + wb;

        float acc0 = 0.f, acc1 = 0.f, acc2 = 0.f, acc3 = 0.f;
        float acc4 = 0.f, acc5 = 0.f, acc6 = 0.f, acc7 = 0.f;

        // t-corner 0: two gathers, then FMA.
        {
            uint4 ua = __ldg((const uint4*)(bg + r00));
            uint4 ub = __ldg((const uint4*)(bg + r01));
            const float wc_a = wta0 * whb0 * wwq;
            const float wc_b = wta0 * whb1 * wwq;
            float2 f;
            f = __half22float2(u_to_h2(ua.x)); acc0 = fmaf(wc_a, f.x, acc0); acc1 = fmaf(wc_a, f.y, acc1);
            f = __half22float2(u_to_h2(ua.y)); acc2 = fmaf(wc_a, f.x, acc2); acc3 = fmaf(wc_a, f.y, acc3);
            f = __half22float2(u_to_h2(ua.z)); acc4 = fmaf(wc_a, f.x, acc4); acc5 = fmaf(wc_a, f.y, acc5);
            f = __half22float2(u_to_h2(ua.w)); acc6 = fmaf(wc_a, f.x, acc6); acc7 = fmaf(wc_a, f.y, acc7);
            f = __half22float2(u_to_h2(ub.x)); acc0 = fmaf(wc_b, f.x, acc0); acc1 = fmaf(wc_b, f.y, acc1);
            f = __half22float2(u_to_h2(ub.y)); acc2 = fmaf(wc_b, f.x, acc2); acc3 = fmaf(wc_b, f.y, acc3);
            f = __half22float2(u_to_h2(ub.z)); acc4 = fmaf(wc_b, f.x, acc4); acc5 = fmaf(wc_b, f.y, acc5);
            f = __half22float2(u_to_h2(ub.w)); acc6 = fmaf(wc_b, f.x, acc6); acc7 = fmaf(wc_b, f.y, acc7);
        }
        // t-corner 1: two gathers, then FMA.
        {
            uint4 ua = __ldg((const uint4*)(bg + r10));
            uint4 ub = __ldg((const uint4*)(bg + r11));
            const float wc_a = wta1 * whb0 * wwq;
            const float wc_b = wta1 * whb1 * wwq;
            float2 f;
            f = __half22float2(u_to_h2(ua.x)); acc0 = fmaf(wc_a, f.x, acc0); acc1 = fmaf(wc_a, f.y, acc1);
            f = __half22float2(u_to_h2(ua.y)); acc2 = fmaf(wc_a, f.x, acc2); acc3 = fmaf(wc_a, f.y, acc3);
            f = __half22float2(u_to_h2(ua.z)); acc4 = fmaf(wc_a, f.x, acc4); acc5 = fmaf(wc_a, f.y, acc5);
            f = __half22float2(u_to_h2(ua.w)); acc6 = fmaf(wc_a, f.x, acc6); acc7 = fmaf(wc_a, f.y, acc7);
            f = __half22float2(u_to_h2(ub.x)); acc0 = fmaf(wc_b, f.x, acc0); acc1 = fmaf(wc_b, f.y, acc1);
            f = __half22float2(u_to_h2(ub.y)); acc2 = fmaf(wc_b, f.x, acc2); acc3 = fmaf(wc_b, f.y, acc3);
            f = __half22float2(u_to_h2(ub.z)); acc4 = fmaf(wc_b, f.x, acc4); acc5 = fmaf(wc_b, f.y, acc5);
            f = __half22float2(u_to_h2(ub.w)); acc6 = fmaf(wc_b, f.x, acc6); acc7 = fmaf(wc_b, f.y, acc7);
        }

        // Combine the two w-corners (lane pairs differ only in bit0).
        acc0 += __shfl_xor_sync(0xFFFFFFFFu, acc0, 1);
        acc1 += __shfl_xor_sync(0xFFFFFFFFu, acc1, 1);
        acc2 += __shfl_xor_sync(0xFFFFFFFFu, acc2, 1);
        acc3 += __shfl_xor_sync(0xFFFFFFFFu, acc3, 1);
        acc4 += __shfl_xor_sync(0xFFFFFFFFu, acc4, 1);
        acc5 += __shfl_xor_sync(0xFFFFFFFFu, acc5, 1);
        acc6 += __shfl_xor_sync(0xFFFFFFFFu, acc6, 1);
        acc7 += __shfl_xor_sync(0xFFFFFFFFu, acc7, 1);

        if (wq == 0) {
            if (!g_general) {
                // Streaming stores: out is write-once, keep it out of L2.
                float* ob = out + ((size_t)(b * CC + g * CG) * TT + t) * HW
                                + (size_t)h * WW + w;
                __stcs(ob,           acc0);
                __stcs(ob + THW,     acc1);
                __stcs(ob + 2*THW,   acc2);
                __stcs(ob + 3*THW,   acc3);
                __stcs(ob + 4*THW,   acc4);
                __stcs(ob + 5*THW,   acc5);
                __stcs(ob + 6*THW,   acc6);
                __stcs(ob + 7*THW,   acc7);
            } else {
                float* dst = g_samp + ((size_t)(b * DG + g) * THW
                             + (size_t)t * HW + (size_t)h * WW + w) * CG;
                ((float4*)dst)[0] = make_float4(acc0, acc1, acc2, acc3);
                ((float4*)dst)[1] = make_float4(acc4, acc5, acc6, acc7);
            }
        }
    }
}

// General 1x1x1 conv path (early-exits when weight is identity).
__global__ __launch_bounds__(256, 4)
void conv_kernel(const float* __restrict__ wgt,
                 const float* __restrict__ bias,
                 float* __restrict__ out) {
    if (!g_general) return;
    const int base = (blockIdx.x * 256 + threadIdx.x) * 8;
#pragma unroll 1
    for (int k = 0; k < 8; k++) {
        const int p = base + k;                 // pixel in [0, B*THW)
        const int b = p / THW;
        const int r = p - b * THW;

        float sv[CC];
#pragma unroll
        for (int g = 0; g < DG; g++) {
            const float* src = g_samp + ((size_t)(b * DG + g) * THW + r) * CG;
#pragma unroll
            for (int c = 0; c < CG; c++) sv[g * CG + c] = src[c];
        }
#pragma unroll 4
        for (int o = 0; o < CC; o++) {
            float a = bias[o];
#pragma unroll 16
            for (int c = 0; c < CC; c++)
                a = fmaf(wgt[o * CC + c], sv[c], a);
            out[(size_t)(b * CC + o) * THW + r] = a;
        }
    }
}

extern "C" void kernel_launch(void* const* d_in, const int* in_sizes, int n_in,
                              void* d_out, int out_size) {
    const float* x    = (const float*)d_in[0];
    const float* off  = (const float*)d_in[1];
    const float* wgt  = (const float*)d_in[2];
    const float* bias = (const float*)d_in[3];
    float* out = (float*)d_out;

    // Two-chunk pipeline (2 batches per chunk): transpose of chunk 1 overlaps
    // deform of chunk 0. Each deform chunk is 1024 blocks (~1.7 waves) so
    // cross-wave load balancing is preserved (R14 lesson: 512-block chunks
    // run as one wave and pay the full per-CTA spread).
    cudaStream_t s1;
    cudaStreamCreateWithFlags(&s1, cudaStreamNonBlocking);
    cudaEvent_t eFork;
    cudaEventCreateWithFlags(&eFork, cudaEventDisableTiming);
    cudaEventRecord(eFork, 0);
    cudaStreamWaitEvent(s1, eFork, 0);

    const int ntrans_c  = (2 * DG * THW) / 256;   // 8192 blocks per 2-batch chunk
    const int ndeform_c = 2 * DG * 16 * 4;        // 1024 blocks per 2-batch chunk

    for (int c = 0; c < 2; c++) {
        const int bbase = c * 2;
        transpose_kernel<<<ntrans_c, 256, 0, s1>>>(x, wgt, bias, bbase);
        cudaEvent_t eT;
        cudaEventCreateWithFlags(&eT, cudaEventDisableTiming);
        cudaEventRecord(eT, s1);
        cudaStreamWaitEvent(0, eT, 0);
        deform_kernel<<<ndeform_c, 512>>>(off, out, bbase);
    }

    conv_kernel<<<(BB * THW) / (256 * 8), 256>>>(wgt, bias, out);
}

// round 16
// speedup vs baseline: 1.1580x; 1.0362x over previous
#include <cuda_runtime.h>
#include <cuda_fp16.h>
#include <cstdint>

// Problem constants (fixed by the reference).
#define BB 4
#define CC 64
#define TT 8
#define HH 128
#define WW 128
#define DG 8
#define CG 8            // channels per deformable group = CC/DG
#define HW (HH*WW)      // 16384
#define THW (TT*HH*WW)  // 131072

// Bit-cast helpers.
__device__ __forceinline__ unsigned h2_to_u(__half2 h) {
    union { __half2 h; unsigned u; } c; c.h = h; return c.u;
}
__device__ __forceinline__ __half2 u_to_h2(unsigned u) {
    union { unsigned u; __half2 h; } c; c.u = u; return c.h;
}

// Channel-last fp16 scratch: xT[b][g][t][h][w][c8] (16 B per pixel-group).
__device__ __half g_xT[(size_t)BB * DG * TT * HH * WW * CG];
// Sampled values (fp32) for the general-weight path.
__device__ float g_samp[(size_t)BB * DG * TT * HW * CG];

// Flag: 0 if weight==Identity and bias==0 (fast path), 1 otherwise.
__device__ int g_general;

// Transpose [B,C,T,H,W] fp32 -> [B,G,T,H,W,C8] fp16. No smem: one thread per
// output pixel-group; 8 coalesced streaming LDG.32 + 1 STG.128.
// Block 0 additionally computes g_general from weight/bias.
__global__ __launch_bounds__(256, 8)
void transpose_kernel(const float* __restrict__ x,
                      const float* __restrict__ wgt,
                      const float* __restrict__ bias) {
    if (blockIdx.x == 0) {
        __shared__ int sbad;
        if (threadIdx.x == 0) sbad = 0;
        __syncthreads();
        int bad = 0;
        for (int i = threadIdx.x; i < CC * CC; i += 256) {
            float e = ((i >> 6) == (i & 63)) ? 1.0f : 0.0f;
            if (wgt[i] != e) bad = 1;
        }
        if (threadIdx.x < CC && bias[threadIdx.x] != 0.0f) bad = 1;
        if (bad) atomicOr(&sbad, 1);
        __syncthreads();
        if (threadIdx.x == 0) g_general = sbad;
        __syncthreads();
    }

    // Linear index over [B][DG][T][H][W].
    const int p  = blockIdx.x * 256 + threadIdx.x;
    const int hw = p & (HW - 1);
    const int t  = (p >> 14) & 7;
    const int g  = (p >> 17) & 7;
    const int b  = p >> 20;

    // Streaming reads: x is read exactly once; don't pollute L2 with it.
    const float* src = x + ((size_t)(b * CC + g * CG) * TT + t) * HW + hw;
    float v0 = __ldcs(src);
    float v1 = __ldcs(src + THW);
    float v2 = __ldcs(src + 2 * THW);
    float v3 = __ldcs(src + 3 * THW);
    float v4 = __ldcs(src + 4 * THW);
    float v5 = __ldcs(src + 5 * THW);
    float v6 = __ldcs(src + 6 * THW);
    float v7 = __ldcs(src + 7 * THW);

    uint4 o;
    o.x = h2_to_u(__floats2half2_rn(v0, v1));
    o.y = h2_to_u(__floats2half2_rn(v2, v3));
    o.z = h2_to_u(__floats2half2_rn(v4, v5));
    o.w = h2_to_u(__floats2half2_rn(v6, v7));
    ((uint4*)g_xT)[p] = o;
}

// Gather. Block = (b, g, 8h x 32w tile), looping t = 0..7 internally.
// 512 threads = 256 pixels x 2 w-corner threads; 4 blocks/SM target.
// Combine step uses a 4-value exchange (instead of 8): thread wq sends the
// partner's channel-half partials, receives its own; BOTH threads then store
// 4 channels each (all lanes active) -> fewer shfl/adds/stores per iter.
__global__ __launch_bounds__(512, 4)
void deform_kernel(const float* __restrict__ off,
                   float* __restrict__ out) {
    const int n  = blockIdx.x;
    const int wt = n & 3;            // w tile (4)
    const int ht = (n >> 2) & 15;    // h tile (16)
    const int g  = (n >> 6) & 7;
    const int b  = n >> 9;

    const int wq = threadIdx.x & 1;          // w-corner select
    const int wl = (threadIdx.x >> 1) & 31;
    const int hl = threadIdx.x >> 6;         // 0..7
    const int w  = (wt << 5) + wl;
    const int h  = (ht << 3) + hl;

    const char* bg  = (const char*)(g_xT + (size_t)(b * DG + g) * THW * CG);
    const int   so0 = ((b * (3 * DG) + g * 3) * TT) * HW + h * WW + w;

    // This thread's output channel base (channels wq*4 .. wq*4+3).
    float* const obase = out + ((size_t)(b * CC + g * CG + wq * 4) * TT) * HW
                             + (size_t)h * WW + w;

    // Prologue: load offsets for t=0 (streaming — read once).
    float ot = __ldcs(off + so0);
    float oh = __ldcs(off + so0 + THW);
    float ow = __ldcs(off + so0 + 2 * THW);

    for (int t = 0; t < TT; ++t) {
        const float gt = (float)t + ot;
        const float gh = (float)h + oh;
        const float gw = (float)w + ow;

        // Pipelined load of next iteration's offsets.
        if (t + 1 < TT) {
            const int so = so0 + (t + 1) * HW;
            ot = __ldcs(off + so);
            oh = __ldcs(off + so + THW);
            ow = __ldcs(off + so + 2 * THW);
        }

        const float ftf = floorf(gt), fhf = floorf(gh), fwf = floorf(gw);
        const int   t0 = (int)ftf,    h0 = (int)fhf,    w0 = (int)fwf;
        const float dt = gt - ftf,    dh = gh - fhf,    dw = gw - fwf;

        float wta0 = (1.0f - dt) * (((unsigned)t0       < (unsigned)TT) ? 1.0f : 0.0f);
        float wta1 = dt          * (((unsigned)(t0 + 1) < (unsigned)TT) ? 1.0f : 0.0f);
        float whb0 = (1.0f - dh) * (((unsigned)h0       < (unsigned)HH) ? 1.0f : 0.0f);
        float whb1 = dh          * (((unsigned)(h0 + 1) < (unsigned)HH) ? 1.0f : 0.0f);
        const int tc0 = min(TT - 1, max(0, t0));
        const int tc1 = min(TT - 1, max(0, t0 + 1));
        const int hc0 = min(HH - 1, max(0, h0));
        const int hc1 = min(HH - 1, max(0, h0 + 1));

        // This thread's w-corner.
        const int   wcm = w0 + wq;
        const float wwq = (wq ? dw : (1.0f - dw))
                        * (((unsigned)wcm < (unsigned)WW) ? 1.0f : 0.0f);
        const unsigned wb = (unsigned)min(WW - 1, max(0, wcm)) * 16u;

        // 32-bit row byte-offsets within this (b,g) slice (< 2 MB).
        const unsigned RB = (unsigned)(WW * CG * 2);   // bytes per row
        const unsigned r00 = (unsigned)(tc0 * HH + hc0) * RB + wb;
        const unsigned r01 = (unsigned)(tc0 * HH + hc1) * RB + wb;
        const unsigned r10 = (unsigned)(tc1 * HH + hc0) * RB + wb;
        const unsigned r11 = (unsigned)(tc1 * HH + hc1) * RB + wb;

        float acc0 = 0.f, acc1 = 0.f, acc2 = 0.f, acc3 = 0.f;
        float acc4 = 0.f, acc5 = 0.f, acc6 = 0.f, acc7 = 0.f;

        // t-corner 0: two gathers, then FMA.
        {
            uint4 ua = __ldg((const uint4*)(bg + r00));
            uint4 ub = __ldg((const uint4*)(bg + r01));
            const float wc_a = wta0 * whb0 * wwq;
            const float wc_b = wta0 * whb1 * wwq;
            float2 f;
            f = __half22float2(u_to_h2(ua.x)); acc0 = fmaf(wc_a, f.x, acc0); acc1 = fmaf(wc_a, f.y, acc1);
            f = __half22float2(u_to_h2(ua.y)); acc2 = fmaf(wc_a, f.x, acc2); acc3 = fmaf(wc_a, f.y, acc3);
            f = __half22float2(u_to_h2(ua.z)); acc4 = fmaf(wc_a, f.x, acc4); acc5 = fmaf(wc_a, f.y, acc5);
            f = __half22float2(u_to_h2(ua.w)); acc6 = fmaf(wc_a, f.x, acc6); acc7 = fmaf(wc_a, f.y, acc7);
            f = __half22float2(u_to_h2(ub.x)); acc0 = fmaf(wc_b, f.x, acc0); acc1 = fmaf(wc_b, f.y, acc1);
            f = __half22float2(u_to_h2(ub.y)); acc2 = fmaf(wc_b, f.x, acc2); acc3 = fmaf(wc_b, f.y, acc3);
            f = __half22float2(u_to_h2(ub.z)); acc4 = fmaf(wc_b, f.x, acc4); acc5 = fmaf(wc_b, f.y, acc5);
            f = __half22float2(u_to_h2(ub.w)); acc6 = fmaf(wc_b, f.x, acc6); acc7 = fmaf(wc_b, f.y, acc7);
        }
        // t-corner 1: two gathers, then FMA.
        {
            uint4 ua = __ldg((const uint4*)(bg + r10));
            uint4 ub = __ldg((const uint4*)(bg + r11));
            const float wc_a = wta1 * whb0 * wwq;
            const float wc_b = wta1 * whb1 * wwq;
            float2 f;
            f = __half22float2(u_to_h2(ua.x)); acc0 = fmaf(wc_a, f.x, acc0); acc1 = fmaf(wc_a, f.y, acc1);
            f = __half22float2(u_to_h2(ua.y)); acc2 = fmaf(wc_a, f.x, acc2); acc3 = fmaf(wc_a, f.y, acc3);
            f = __half22float2(u_to_h2(ua.z)); acc4 = fmaf(wc_a, f.x, acc4); acc5 = fmaf(wc_a, f.y, acc5);
            f = __half22float2(u_to_h2(ua.w)); acc6 = fmaf(wc_a, f.x, acc6); acc7 = fmaf(wc_a, f.y, acc7);
            f = __half22float2(u_to_h2(ub.x)); acc0 = fmaf(wc_b, f.x, acc0); acc1 = fmaf(wc_b, f.y, acc1);
            f = __half22float2(u_to_h2(ub.y)); acc2 = fmaf(wc_b, f.x, acc2); acc3 = fmaf(wc_b, f.y, acc3);
            f = __half22float2(u_to_h2(ub.z)); acc4 = fmaf(wc_b, f.x, acc4); acc5 = fmaf(wc_b, f.y, acc5);
            f = __half22float2(u_to_h2(ub.w)); acc6 = fmaf(wc_b, f.x, acc6); acc7 = fmaf(wc_b, f.y, acc7);
        }

        // 4-value exchange: thread wq keeps channels [4*wq, 4*wq+4) and sends
        // the partner's half. recv[i] = partner's partial for channel 4*wq+i.
        const float s0 = wq ? acc0 : acc4;
        const float s1 = wq ? acc1 : acc5;
        const float s2 = wq ? acc2 : acc6;
        const float s3 = wq ? acc3 : acc7;
        const float r0 = __shfl_xor_sync(0xFFFFFFFFu, s0, 1);
        const float r1 = __shfl_xor_sync(0xFFFFFFFFu, s1, 1);
        const float r2 = __shfl_xor_sync(0xFFFFFFFFu, s2, 1);
        const float r3 = __shfl_xor_sync(0xFFFFFFFFu, s3, 1);
        const float o0 = (wq ? acc4 : acc0) + r0;
        const float o1 = (wq ? acc5 : acc1) + r1;
        const float o2 = (wq ? acc6 : acc2) + r2;
        const float o3 = (wq ? acc7 : acc3) + r3;

        if (!g_general) {
            // Streaming stores; every lane stores its own 4 channels.
            float* ob = obase + (size_t)t * HW;
            __stcs(ob,           o0);
            __stcs(ob + THW,     o1);
            __stcs(ob + 2*THW,   o2);
            __stcs(ob + 3*THW,   o3);
        } else {
            float* dst = g_samp + ((size_t)(b * DG + g) * THW
                         + (size_t)t * HW + (size_t)h * WW + w) * CG;
            ((float4*)dst)[wq] = make_float4(o0, o1, o2, o3);
        }
    }
}

// General 1x1x1 conv path (early-exits when weight is identity).
__global__ __launch_bounds__(256, 4)
void conv_kernel(const float* __restrict__ wgt,
                 const float* __restrict__ bias,
                 float* __restrict__ out) {
    if (!g_general) return;
    const int base = (blockIdx.x * 256 + threadIdx.x) * 8;
#pragma unroll 1
    for (int k = 0; k < 8; k++) {
        const int p = base + k;                 // pixel in [0, B*THW)
        const int b = p / THW;
        const int r = p - b * THW;

        float sv[CC];
#pragma unroll
        for (int g = 0; g < DG; g++) {
            const float* src = g_samp + ((size_t)(b * DG + g) * THW + r) * CG;
#pragma unroll
            for (int c = 0; c < CG; c++) sv[g * CG + c] = src[c];
        }
#pragma unroll 4
        for (int o = 0; o < CC; o++) {
            float a = bias[o];
#pragma unroll 16
            for (int c = 0; c < CC; c++)
                a = fmaf(wgt[o * CC + c], sv[c], a);
            out[(size_t)(b * CC + o) * THW + r] = a;
        }
    }
}

extern "C" void kernel_launch(void* const* d_in, const int* in_sizes, int n_in,
                              void* d_out, int out_size) {
    const float* x    = (const float*)d_in[0];
    const float* off  = (const float*)d_in[1];
    const float* wgt  = (const float*)d_in[2];
    const float* bias = (const float*)d_in[3];
    float* out = (float*)d_out;

    // Serial launcher (R15 lesson: transpose/deform overlap loses — both are
    // SM-local-resource bound, so concurrency just splits SM time).
    const int ntrans = (BB * DG * THW) / 256;      // 16384
    transpose_kernel<<<ntrans, 256>>>(x, wgt, bias);

    const int nblocks = BB * DG * 16 * 4;          // 2048, loop t inside
    deform_kernel<<<nblocks, 512>>>(off, out);

    conv_kernel<<<(BB * THW) / (256 * 8), 256>>>(wgt, bias, out);
}